// round 1
// baseline (speedup 1.0000x reference)
#include <cuda_runtime.h>
#include <cstddef>

// Problem constants
#define N_USER  100000
#define N_MOVIE 20000
#define D_IN    64
#define HID     128
#define OUT_D   64
#define NEDGE   600000

// ---------------------------------------------------------------------------
// Scratch (device globals: no allocation allowed in kernel_launch)
// ---------------------------------------------------------------------------
__device__ float g_agg_user [N_USER  * D_IN];   // conv1 aggregation (movie -> user), width 64
__device__ float g_agg_movie[N_MOVIE * D_IN];   // conv2 aggregation (user -> movie), width 64
__device__ float g_agg_user2[N_USER  * HID];    // conv3 aggregation of projected movie feats, width 128
__device__ float g_deg_user [N_USER];
__device__ float g_deg_movie[N_MOVIE];
__device__ float g_user_x  [N_USER  * HID];
__device__ float g_movie_x [N_MOVIE * HID];
__device__ float g_movieP  [N_MOVIE * HID];     // movie_x @ W3l (projected BEFORE aggregation)
__device__ float g_user_h  [N_USER  * HID];

// ---------------------------------------------------------------------------
// Helpers: packed f32x2 FMA (Blackwell), vector global reduction
// ---------------------------------------------------------------------------
__device__ __forceinline__ unsigned long long pack2(float x, float y) {
    unsigned long long r;
    asm("mov.b64 %0, {%1, %2};" : "=l"(r) : "f"(x), "f"(y));
    return r;
}
__device__ __forceinline__ float2 unpack2(unsigned long long v) {
    float2 r;
    asm("mov.b64 {%0, %1}, %2;" : "=f"(r.x), "=f"(r.y) : "l"(v));
    return r;
}
__device__ __forceinline__ unsigned long long ffma2u(unsigned long long a,
                                                     unsigned long long b,
                                                     unsigned long long c) {
    unsigned long long d;
    asm("fma.rn.f32x2 %0, %1, %2, %3;" : "=l"(d) : "l"(a), "l"(b), "l"(c));
    return d;
}
__device__ __forceinline__ void red4(float* p, float4 v) {
    asm volatile("red.global.add.v4.f32 [%0], {%1, %2, %3, %4};"
                 :: "l"(p), "f"(v.x), "f"(v.y), "f"(v.z), "f"(v.w) : "memory");
}

// ---------------------------------------------------------------------------
// Zero all accumulation scratch (float4 grid-stride over cascaded ranges)
// ---------------------------------------------------------------------------
#define AU2_F4 (N_USER  * HID  / 4)   // 3,200,000
#define AU_F4  (N_USER  * D_IN / 4)   // 1,600,000
#define AM_F4  (N_MOVIE * D_IN / 4)   //   320,000
#define DU_F4  (N_USER  / 4)          //    25,000
#define DM_F4  (N_MOVIE / 4)          //     5,000
#define ZTOT   (AU2_F4 + AU_F4 + AM_F4 + DU_F4 + DM_F4)

__global__ void zero_kernel() {
    long long i = (long long)blockIdx.x * blockDim.x + threadIdx.x;
    float4 z = make_float4(0.f, 0.f, 0.f, 0.f);
    if (i < AU2_F4) { ((float4*)g_agg_user2)[i] = z; return; }
    i -= AU2_F4;
    if (i < AU_F4)  { ((float4*)g_agg_user)[i]  = z; return; }
    i -= AU_F4;
    if (i < AM_F4)  { ((float4*)g_agg_movie)[i] = z; return; }
    i -= AM_F4;
    if (i < DU_F4)  { ((float4*)g_deg_user)[i]  = z; return; }
    i -= DU_F4;
    if (i < DM_F4)  { ((float4*)g_deg_movie)[i] = z; return; }
}

// ---------------------------------------------------------------------------
// Edge pass 1 (fused conv1 + conv2 gather):
//   agg_user[u]  += x_movie[m]   (64 f)
//   agg_movie[m] += x_user[u]    (64 f)
//   deg_user[u] += 1, deg_movie[m] += 1
// One thread per (edge, 16B chunk): 16 chunks/edge.
// ---------------------------------------------------------------------------
__global__ __launch_bounds__(256) void edge_pass1(
    const int* __restrict__ eu, const int* __restrict__ em,
    const float* __restrict__ xu, const float* __restrict__ xm)
{
    long long gid = (long long)blockIdx.x * blockDim.x + threadIdx.x;
    if (gid >= (long long)NEDGE * 16) return;
    int e = (int)(gid >> 4);
    int c = (int)(gid & 15);
    int u = eu[e];
    int m = em[e];
    float4 vm = ((const float4*)xm)[(long long)m * 16 + c];
    red4(&g_agg_user[(long long)u * D_IN + c * 4], vm);
    float4 vu = ((const float4*)xu)[(long long)u * 16 + c];
    red4(&g_agg_movie[(long long)m * D_IN + c * 4], vu);
    if (c == 0) {
        atomicAdd(&g_deg_user[u], 1.0f);
        atomicAdd(&g_deg_movie[m], 1.0f);
    }
}

// ---------------------------------------------------------------------------
// Edge pass 2 (conv3 gather of projected features):
//   agg_user2[u] += movieP[m]   (128 f)
// One thread per (edge, 16B chunk): 32 chunks/edge.
// ---------------------------------------------------------------------------
__global__ __launch_bounds__(256) void edge_pass2(
    const int* __restrict__ eu, const int* __restrict__ em)
{
    long long gid = (long long)blockIdx.x * blockDim.x + threadIdx.x;
    if (gid >= (long long)NEDGE * 32) return;
    int e = (int)(gid >> 5);
    int c = (int)(gid & 31);
    int u = eu[e];
    int m = em[e];
    float4 v = ((const float4*)g_movieP)[(long long)m * 32 + c];
    red4(&g_agg_user2[(long long)u * HID + c * 4], v);
}

// ---------------------------------------------------------------------------
// Fused combine / linear kernel:
//   out[r] = act( [AGG: agg[r]/max(deg,1) (@Wl if WL, else added directly)]
//                 + x[r] @ Wr + [BIAS: b] )
// Packed f32x2 math: weights in smem as natural pairs, row operands staged
// DUPLICATED in smem so each inner step is LDS.64 broadcast + FFMA2.
// blockDim = (N/2, 256/(N/2)); 8 rows per block iteration; persistent grid.
// ---------------------------------------------------------------------------
template<int K, int N, bool WL, bool AGG, bool RELU, bool BIAS>
__global__ __launch_bounds__(256) void combine_kernel(
    const float* __restrict__ agg, const float* __restrict__ deg,
    const float* __restrict__ x,
    const float* __restrict__ Wl, const float* __restrict__ Wr,
    const float* __restrict__ bias,
    float* __restrict__ out, int nrows)
{
    constexpr int CP   = N / 2;        // column pairs
    constexpr int YG   = 256 / CP;     // row groups
    constexpr int ROWS = 8;            // rows per block iteration
    constexpr int RPT  = ROWS / YG;    // rows per thread

    extern __shared__ __align__(16) char smem[];
    float* sWr = (float*)smem;                       // [K][N]
    float* sWl = sWr + K * N;                        // [K][N] (only if WL)
    unsigned long long* sx = (unsigned long long*)(smem + (size_t)(WL ? 2 : 1) * K * N * 4);
    unsigned long long* sa = sx + ROWS * K;          // only if WL

    const int tid = threadIdx.y * CP + threadIdx.x;

    // Stage weights once per block
    for (int i = tid; i < K * N / 4; i += 256) {
        ((float4*)sWr)[i] = ((const float4*)Wr)[i];
        if constexpr (WL) ((float4*)sWl)[i] = ((const float4*)Wl)[i];
    }

    const int ntiles = (nrows + ROWS - 1) / ROWS;
    for (int tile = blockIdx.x; tile < ntiles; tile += gridDim.x) {
        const int row0 = tile * ROWS;
        __syncthreads();   // also covers the initial weight staging
        // Stage 8 rows of x (and scaled agg) as duplicated f32 pairs
        for (int i = tid; i < ROWS * K; i += 256) {
            int r = i / K, k = i - r * K;
            int row = row0 + r;
            float v = 0.f, va = 0.f;
            if (row < nrows) {
                v = x[(size_t)row * K + k];
                if constexpr (WL)
                    va = agg[(size_t)row * K + k] * (1.0f / fmaxf(deg[row], 1.0f));
            }
            sx[i] = pack2(v, v);
            if constexpr (WL) sa[i] = pack2(va, va);
        }
        __syncthreads();

        const int c  = threadIdx.x;
        const int yy = threadIdx.y;
        unsigned long long acc[RPT];
        #pragma unroll
        for (int r = 0; r < RPT; r++) {
            int row = row0 + yy * RPT + r;
            float2 a0 = make_float2(0.f, 0.f);
            if constexpr (BIAS) a0 = ((const float2*)bias)[c];
            if constexpr (AGG && !WL) {
                if (row < nrows) {
                    float id = 1.0f / fmaxf(deg[row], 1.0f);
                    float2 g = ((const float2*)agg)[(size_t)row * CP + c];
                    a0.x += g.x * id;
                    a0.y += g.y * id;
                }
            }
            acc[r] = pack2(a0.x, a0.y);
        }

        const unsigned long long* sWr2 = (const unsigned long long*)sWr;
        const unsigned long long* sWl2 = (const unsigned long long*)sWl;
        #pragma unroll 8
        for (int k = 0; k < K; k++) {
            unsigned long long wr2 = sWr2[k * CP + c];
            unsigned long long wl2 = 0;
            if constexpr (WL) wl2 = sWl2[k * CP + c];
            #pragma unroll
            for (int r = 0; r < RPT; r++) {
                int rl = yy * RPT + r;
                acc[r] = ffma2u(sx[rl * K + k], wr2, acc[r]);
                if constexpr (WL) acc[r] = ffma2u(sa[rl * K + k], wl2, acc[r]);
            }
        }

        #pragma unroll
        for (int r = 0; r < RPT; r++) {
            int row = row0 + yy * RPT + r;
            if (row < nrows) {
                float2 o = unpack2(acc[r]);
                if constexpr (RELU) { o.x = fmaxf(o.x, 0.f); o.y = fmaxf(o.y, 0.f); }
                ((float2*)out)[(size_t)row * CP + c] = o;
            }
        }
    }
}

// ---------------------------------------------------------------------------
// kernel_launch
// Input order: x_user, x_movie, edge_user, edge_movie,
//              W1l, W1r, b1, W2l, W2r, b2, W3l, W3r, b3,
//              Wlin1, blin1, Wlin2, blin2
// Output: out_user [100000,64] followed by out_movie [20000,64]
// ---------------------------------------------------------------------------
extern "C" void kernel_launch(void* const* d_in, const int* in_sizes, int n_in,
                              void* d_out, int out_size) {
    const float* x_user  = (const float*)d_in[0];
    const float* x_movie = (const float*)d_in[1];
    const int*   eu      = (const int*)d_in[2];
    const int*   em      = (const int*)d_in[3];
    const float* W1l     = (const float*)d_in[4];
    const float* W1r     = (const float*)d_in[5];
    const float* b1      = (const float*)d_in[6];
    const float* W2l     = (const float*)d_in[7];
    const float* W2r     = (const float*)d_in[8];
    const float* b2      = (const float*)d_in[9];
    const float* W3l     = (const float*)d_in[10];
    const float* W3r     = (const float*)d_in[11];
    const float* b3      = (const float*)d_in[12];
    const float* Wlin1   = (const float*)d_in[13];
    const float* blin1   = (const float*)d_in[14];
    const float* Wlin2   = (const float*)d_in[15];
    const float* blin2   = (const float*)d_in[16];

    float* out_user  = (float*)d_out;
    float* out_movie = out_user + (size_t)N_USER * OUT_D;

    // Resolve scratch addresses (query API, capture-safe)
    float *p_agg_user, *p_agg_movie, *p_agg_user2, *p_deg_user, *p_deg_movie;
    float *p_user_x, *p_movie_x, *p_movieP, *p_user_h;
    cudaGetSymbolAddress((void**)&p_agg_user,  g_agg_user);
    cudaGetSymbolAddress((void**)&p_agg_movie, g_agg_movie);
    cudaGetSymbolAddress((void**)&p_agg_user2, g_agg_user2);
    cudaGetSymbolAddress((void**)&p_deg_user,  g_deg_user);
    cudaGetSymbolAddress((void**)&p_deg_movie, g_deg_movie);
    cudaGetSymbolAddress((void**)&p_user_x,    g_user_x);
    cudaGetSymbolAddress((void**)&p_movie_x,   g_movie_x);
    cudaGetSymbolAddress((void**)&p_movieP,    g_movieP);
    cudaGetSymbolAddress((void**)&p_user_h,    g_user_h);

    // smem sizes
    const int SM_CONV12 = 2 * D_IN * HID * 4 + 8 * D_IN * 8 * 2;  // 73728
    const int SM_HH     = HID * HID * 4 + 8 * HID * 8;            // 73728
    const int SM_HO     = HID * OUT_D * 4 + 8 * HID * 8;          // 40960

    cudaFuncSetAttribute((const void*)combine_kernel<D_IN, HID, true,  true,  true,  true>,
                         cudaFuncAttributeMaxDynamicSharedMemorySize, SM_CONV12);
    cudaFuncSetAttribute((const void*)combine_kernel<HID, HID, false, false, false, false>,
                         cudaFuncAttributeMaxDynamicSharedMemorySize, SM_HH);
    cudaFuncSetAttribute((const void*)combine_kernel<HID, HID, false, true,  true,  true>,
                         cudaFuncAttributeMaxDynamicSharedMemorySize, SM_HH);
    cudaFuncSetAttribute((const void*)combine_kernel<HID, OUT_D, false, false, false, true>,
                         cudaFuncAttributeMaxDynamicSharedMemorySize, SM_HO);

    const int GRID_PERSIST = 444;  // ~3 blocks/SM at 72KB smem on 148 SMs

    // 1. Zero accumulators
    zero_kernel<<<(ZTOT + 255) / 256, 256>>>();

    // 2. Fused edge gather for conv1 + conv2 (+ degrees)
    edge_pass1<<<(NEDGE * 16 + 255) / 256, 256>>>(eu, em, x_user, x_movie);

    // 3. conv1: user_x = relu(agg_user/deg @ W1l + x_user @ W1r + b1)
    combine_kernel<D_IN, HID, true, true, true, true>
        <<<GRID_PERSIST, dim3(HID / 2, 256 / (HID / 2)), SM_CONV12>>>(
            p_agg_user, p_deg_user, x_user, W1l, W1r, b1, p_user_x, N_USER);

    // 4. conv2: movie_x = relu(agg_movie/deg @ W2l + x_movie @ W2r + b2)
    combine_kernel<D_IN, HID, true, true, true, true>
        <<<GRID_PERSIST, dim3(HID / 2, 256 / (HID / 2)), SM_CONV12>>>(
            p_agg_movie, p_deg_movie, x_movie, W2l, W2r, b2, p_movie_x, N_MOVIE);

    // 5. Project movies BEFORE aggregation: movieP = movie_x @ W3l
    combine_kernel<HID, HID, false, false, false, false>
        <<<GRID_PERSIST, dim3(HID / 2, 256 / (HID / 2)), SM_HH>>>(
            nullptr, nullptr, p_movie_x, nullptr, W3l, nullptr, p_movieP, N_MOVIE);

    // 6. Edge gather for conv3 (projected features)
    edge_pass2<<<(NEDGE * 32 + 255) / 256, 256>>>(eu, em);

    // 7. conv3: user_h = relu(agg_user2/deg + user_x @ W3r + b3)
    combine_kernel<HID, HID, false, true, true, true>
        <<<GRID_PERSIST, dim3(HID / 2, 256 / (HID / 2)), SM_HH>>>(
            p_agg_user2, p_deg_user, p_user_x, nullptr, W3r, b3, p_user_h, N_USER);

    // 8. out_user = user_h @ Wlin1 + blin1
    combine_kernel<HID, OUT_D, false, false, false, true>
        <<<GRID_PERSIST, dim3(OUT_D / 2, 256 / (OUT_D / 2)), SM_HO>>>(
            nullptr, nullptr, p_user_h, nullptr, Wlin1, blin1, out_user, N_USER);

    // 9. out_movie = movie_x @ Wlin2 + blin2
    combine_kernel<HID, OUT_D, false, false, false, true>
        <<<GRID_PERSIST, dim3(OUT_D / 2, 256 / (OUT_D / 2)), SM_HO>>>(
            nullptr, nullptr, p_movie_x, nullptr, Wlin2, blin2, out_movie, N_MOVIE);
}

// round 2
// speedup vs baseline: 1.4636x; 1.4636x over previous
#include <cuda_runtime.h>
#include <cstddef>

// Problem constants
#define N_USER  100000
#define N_MOVIE 20000
#define D_IN    64
#define HID     128
#define OUT_D   64
#define NEDGE   600000

// ---------------------------------------------------------------------------
// Scratch (device globals: no allocation allowed anywhere)
// ---------------------------------------------------------------------------
__device__ int g_deg_u[N_USER];
__device__ int g_deg_m[N_MOVIE];
__device__ int g_off_u[N_USER];
__device__ int g_off_m[N_MOVIE];
__device__ int g_cur_u[N_USER];
__device__ int g_cur_m[N_MOVIE];
__device__ int g_adj_u[NEDGE];      // movie index, sorted by user dst
__device__ int g_adj_m[NEDGE];      // user index, sorted by movie dst
__device__ int g_part_u[128];
__device__ int g_part_m[32];

__device__ float g_agg_user [N_USER  * D_IN];   // mean of x_movie over edges
__device__ float g_agg_movie[N_MOVIE * D_IN];   // mean of x_user over edges
__device__ float g_agg_user2[N_USER  * HID];    // mean of movieP over edges
__device__ float g_user_x  [N_USER  * HID];
__device__ float g_movie_x [N_MOVIE * HID];
__device__ float g_movieP  [N_MOVIE * HID];     // movie_x @ W3l (projected BEFORE aggregation)
__device__ float g_user_h  [N_USER  * HID];

// ---------------------------------------------------------------------------
// Packed f32x2 helpers (Blackwell)
// ---------------------------------------------------------------------------
__device__ __forceinline__ unsigned long long pack2(float x, float y) {
    unsigned long long r;
    asm("mov.b64 %0, {%1, %2};" : "=l"(r) : "f"(x), "f"(y));
    return r;
}
__device__ __forceinline__ float2 unpack2(unsigned long long v) {
    float2 r;
    asm("mov.b64 {%0, %1}, %2;" : "=f"(r.x), "=f"(r.y) : "l"(v));
    return r;
}
__device__ __forceinline__ unsigned long long ffma2u(unsigned long long a,
                                                     unsigned long long b,
                                                     unsigned long long c) {
    unsigned long long d;
    asm("fma.rn.f32x2 %0, %1, %2, %3;" : "=l"(d) : "l"(a), "l"(b), "l"(c));
    return d;
}

// ---------------------------------------------------------------------------
// CSR build: zero counts -> histogram -> block scan -> partial scan ->
//            add offsets (+init cursors) -> fill adjacency
// ---------------------------------------------------------------------------
__global__ void zero_counts() {
    int i = blockIdx.x * blockDim.x + threadIdx.x;
    if (i < N_USER)  g_deg_u[i] = 0;
    if (i < N_MOVIE) g_deg_m[i] = 0;
}

__global__ __launch_bounds__(256) void hist_kernel(
    const int* __restrict__ eu, const int* __restrict__ em)
{
    int e = blockIdx.x * blockDim.x + threadIdx.x;
    if (e >= NEDGE) return;
    atomicAdd(&g_deg_u[eu[e]], 1);
    atomicAdd(&g_deg_m[em[e]], 1);
}

__global__ __launch_bounds__(1024) void scan_block_kernel(
    const int* __restrict__ deg, int* __restrict__ off,
    int* __restrict__ part, int n)
{
    __shared__ int s[1024];
    int t = threadIdx.x;
    int i = blockIdx.x * 1024 + t;
    int v = (i < n) ? deg[i] : 0;
    s[t] = v;
    __syncthreads();
    #pragma unroll
    for (int d = 1; d < 1024; d <<= 1) {
        int x = (t >= d) ? s[t - d] : 0;
        __syncthreads();
        s[t] += x;
        __syncthreads();
    }
    if (i < n) off[i] = s[t] - v;          // exclusive
    if (t == 1023) part[blockIdx.x] = s[1023];
}

__global__ __launch_bounds__(128) void scan_partials_kernel(int nu, int nm) {
    __shared__ int s[128];
    int t = threadIdx.x;
    // user partials (<=128)
    int v = (t < nu) ? g_part_u[t] : 0;
    s[t] = v;
    __syncthreads();
    #pragma unroll
    for (int d = 1; d < 128; d <<= 1) {
        int x = (t >= d) ? s[t - d] : 0;
        __syncthreads();
        s[t] += x;
        __syncthreads();
    }
    if (t < nu) g_part_u[t] = s[t] - v;    // exclusive
    __syncthreads();
    // movie partials (<=32)
    v = (t < nm) ? g_part_m[t] : 0;
    s[t] = v;
    __syncthreads();
    #pragma unroll
    for (int d = 1; d < 128; d <<= 1) {
        int x = (t >= d) ? s[t - d] : 0;
        __syncthreads();
        s[t] += x;
        __syncthreads();
    }
    if (t < nm) g_part_m[t] = s[t] - v;
}

__global__ __launch_bounds__(256) void add_offsets_kernel(
    int* __restrict__ off, int* __restrict__ cur,
    const int* __restrict__ part, int n)
{
    int i = blockIdx.x * blockDim.x + threadIdx.x;
    if (i >= n) return;
    int o = off[i] + part[i >> 10];
    off[i] = o;
    cur[i] = o;
}

__global__ __launch_bounds__(256) void fill_kernel(
    const int* __restrict__ eu, const int* __restrict__ em)
{
    int e = blockIdx.x * blockDim.x + threadIdx.x;
    if (e >= NEDGE) return;
    int u = eu[e], m = em[e];
    int su = atomicAdd(&g_cur_u[u], 1);
    g_adj_u[su] = m;
    int sm = atomicAdd(&g_cur_m[m], 1);
    g_adj_m[sm] = u;
}

// ---------------------------------------------------------------------------
// Gather-mean: one warp per destination node, coalesced row reads.
// Writes mean(src over incident edges) (deg=0 -> zeros).
// ---------------------------------------------------------------------------
template<int D>
__global__ __launch_bounds__(256) void gather_mean(
    const float* __restrict__ src, const int* __restrict__ adj,
    const int* __restrict__ off, const int* __restrict__ deg,
    float* __restrict__ dst, int n)
{
    int w = (blockIdx.x * 256 + threadIdx.x) >> 5;
    int lane = threadIdx.x & 31;
    if (w >= n) return;
    int o = off[w], d = deg[w];
    float sc = 1.0f / (float)max(d, 1);
    if constexpr (D == 64) {
        float2 acc = make_float2(0.f, 0.f);
        #pragma unroll 2
        for (int i = 0; i < d; i++) {
            int s = __ldg(&adj[o + i]);
            float2 v = ((const float2*)src)[(size_t)s * 32 + lane];
            acc.x += v.x; acc.y += v.y;
        }
        ((float2*)dst)[(size_t)w * 32 + lane] = make_float2(acc.x * sc, acc.y * sc);
    } else {
        float4 acc = make_float4(0.f, 0.f, 0.f, 0.f);
        #pragma unroll 2
        for (int i = 0; i < d; i++) {
            int s = __ldg(&adj[o + i]);
            float4 v = ((const float4*)src)[(size_t)s * 32 + lane];
            acc.x += v.x; acc.y += v.y; acc.z += v.z; acc.w += v.w;
        }
        ((float4*)dst)[(size_t)w * 32 + lane] =
            make_float4(acc.x * sc, acc.y * sc, acc.z * sc, acc.w * sc);
    }
}

// ---------------------------------------------------------------------------
// Combine / linear kernel:
//   out[r] = act( [WL: agg[r] @ Wl] + [AGG&&!WL: agg[r] added directly]
//                 + x[r] @ Wr + [BIAS: b] )
// agg is already the mean. Packed f32x2 math, weights staged in smem,
// row operands staged as duplicated pairs; 32 rows/tile, RPT rows/thread.
// ---------------------------------------------------------------------------
template<int K, int N, bool WL, bool AGG, bool RELU, bool BIAS>
__global__ __launch_bounds__(256) void combine_kernel(
    const float* __restrict__ agg, const float* __restrict__ x,
    const float* __restrict__ Wl, const float* __restrict__ Wr,
    const float* __restrict__ bias,
    float* __restrict__ out, int nrows)
{
    constexpr int CP   = N / 2;        // column pairs
    constexpr int YG   = 256 / CP;     // row groups
    constexpr int ROWS = 32;           // rows per block iteration
    constexpr int RPT  = ROWS / YG;    // rows per thread (N=128: 8, N=64: 4)

    extern __shared__ __align__(16) char smem[];
    float* sWr = (float*)smem;                       // [K][N]
    float* sWl = sWr + K * N;                        // [K][N] (only if WL)
    unsigned long long* sx = (unsigned long long*)(smem + (size_t)(WL ? 2 : 1) * K * N * 4);
    unsigned long long* sa = sx + ROWS * K;          // only if WL

    const int tid = threadIdx.x;
    const int c  = tid % CP;
    const int yy = tid / CP;

    // Stage weights once per block
    for (int i = tid; i < K * N / 4; i += 256) {
        ((float4*)sWr)[i] = ((const float4*)Wr)[i];
        if constexpr (WL) ((float4*)sWl)[i] = ((const float4*)Wl)[i];
    }

    const int ntiles = (nrows + ROWS - 1) / ROWS;
    for (int tile = blockIdx.x; tile < ntiles; tile += gridDim.x) {
        const int row0 = tile * ROWS;
        __syncthreads();   // also covers the initial weight staging
        // Stage 32 rows as duplicated f32 pairs
        for (int i = tid; i < ROWS * K; i += 256) {
            int r = i / K, k = i - r * K;
            int row = row0 + r;
            float v = 0.f, va = 0.f;
            if (row < nrows) {
                v = x[(size_t)row * K + k];
                if constexpr (WL) va = agg[(size_t)row * K + k];
            }
            sx[i] = pack2(v, v);
            if constexpr (WL) sa[i] = pack2(va, va);
        }
        __syncthreads();

        unsigned long long acc[RPT];
        #pragma unroll
        for (int r = 0; r < RPT; r++) {
            int row = row0 + yy * RPT + r;
            float2 a0 = make_float2(0.f, 0.f);
            if constexpr (BIAS) a0 = ((const float2*)bias)[c];
            if constexpr (AGG && !WL) {
                if (row < nrows) {
                    float2 g = ((const float2*)agg)[(size_t)row * CP + c];
                    a0.x += g.x;
                    a0.y += g.y;
                }
            }
            acc[r] = pack2(a0.x, a0.y);
        }

        const unsigned long long* sWr2 = (const unsigned long long*)sWr;
        const unsigned long long* sWl2 = (const unsigned long long*)sWl;
        #pragma unroll 4
        for (int k = 0; k < K; k += 2) {
            unsigned long long wr0 = sWr2[(k + 0) * CP + c];
            unsigned long long wr1 = sWr2[(k + 1) * CP + c];
            unsigned long long wl0, wl1;
            if constexpr (WL) {
                wl0 = sWl2[(k + 0) * CP + c];
                wl1 = sWl2[(k + 1) * CP + c];
            }
            #pragma unroll
            for (int r = 0; r < RPT; r++) {
                int rl = yy * RPT + r;
                ulonglong2 xv = *(const ulonglong2*)&sx[rl * K + k];   // 16B bcast
                acc[r] = ffma2u(xv.x, wr0, acc[r]);
                acc[r] = ffma2u(xv.y, wr1, acc[r]);
                if constexpr (WL) {
                    ulonglong2 av = *(const ulonglong2*)&sa[rl * K + k];
                    acc[r] = ffma2u(av.x, wl0, acc[r]);
                    acc[r] = ffma2u(av.y, wl1, acc[r]);
                }
            }
        }

        #pragma unroll
        for (int r = 0; r < RPT; r++) {
            int row = row0 + yy * RPT + r;
            if (row < nrows) {
                float2 o = unpack2(acc[r]);
                if constexpr (RELU) { o.x = fmaxf(o.x, 0.f); o.y = fmaxf(o.y, 0.f); }
                ((float2*)out)[(size_t)row * CP + c] = o;
            }
        }
    }
}

// ---------------------------------------------------------------------------
// kernel_launch
// Input order: x_user, x_movie, edge_user, edge_movie,
//              W1l, W1r, b1, W2l, W2r, b2, W3l, W3r, b3,
//              Wlin1, blin1, Wlin2, blin2
// Output: out_user [100000,64] followed by out_movie [20000,64]
// ---------------------------------------------------------------------------
extern "C" void kernel_launch(void* const* d_in, const int* in_sizes, int n_in,
                              void* d_out, int out_size) {
    const float* x_user  = (const float*)d_in[0];
    const float* x_movie = (const float*)d_in[1];
    const int*   eu      = (const int*)d_in[2];
    const int*   em      = (const int*)d_in[3];
    const float* W1l     = (const float*)d_in[4];
    const float* W1r     = (const float*)d_in[5];
    const float* b1      = (const float*)d_in[6];
    const float* W2l     = (const float*)d_in[7];
    const float* W2r     = (const float*)d_in[8];
    const float* b2      = (const float*)d_in[9];
    const float* W3l     = (const float*)d_in[10];
    const float* W3r     = (const float*)d_in[11];
    const float* b3      = (const float*)d_in[12];
    const float* Wlin1   = (const float*)d_in[13];
    const float* blin1   = (const float*)d_in[14];
    const float* Wlin2   = (const float*)d_in[15];
    const float* blin2   = (const float*)d_in[16];

    float* out_user  = (float*)d_out;
    float* out_movie = out_user + (size_t)N_USER * OUT_D;

    // Resolve scratch addresses
    int *p_deg_u, *p_deg_m, *p_off_u, *p_off_m, *p_cur_u, *p_cur_m;
    int *p_adj_u, *p_adj_m, *p_part_u, *p_part_m;
    float *p_agg_user, *p_agg_movie, *p_agg_user2;
    float *p_user_x, *p_movie_x, *p_movieP, *p_user_h;
    cudaGetSymbolAddress((void**)&p_deg_u, g_deg_u);
    cudaGetSymbolAddress((void**)&p_deg_m, g_deg_m);
    cudaGetSymbolAddress((void**)&p_off_u, g_off_u);
    cudaGetSymbolAddress((void**)&p_off_m, g_off_m);
    cudaGetSymbolAddress((void**)&p_cur_u, g_cur_u);
    cudaGetSymbolAddress((void**)&p_cur_m, g_cur_m);
    cudaGetSymbolAddress((void**)&p_adj_u, g_adj_u);
    cudaGetSymbolAddress((void**)&p_adj_m, g_adj_m);
    cudaGetSymbolAddress((void**)&p_part_u, g_part_u);
    cudaGetSymbolAddress((void**)&p_part_m, g_part_m);
    cudaGetSymbolAddress((void**)&p_agg_user,  g_agg_user);
    cudaGetSymbolAddress((void**)&p_agg_movie, g_agg_movie);
    cudaGetSymbolAddress((void**)&p_agg_user2, g_agg_user2);
    cudaGetSymbolAddress((void**)&p_user_x,    g_user_x);
    cudaGetSymbolAddress((void**)&p_movie_x,   g_movie_x);
    cudaGetSymbolAddress((void**)&p_movieP,    g_movieP);
    cudaGetSymbolAddress((void**)&p_user_h,    g_user_h);

    // smem sizes (weights + duplicated-pair row staging)
    const int SM_CONV12 = 2 * D_IN * HID * 4 + 2 * 32 * D_IN * 8;   // 98304
    const int SM_HH     = HID * HID * 4 + 32 * HID * 8;             // 98304
    const int SM_HO     = HID * OUT_D * 4 + 32 * HID * 8;           // 65536

    cudaFuncSetAttribute((const void*)combine_kernel<D_IN, HID, true,  true,  true,  true>,
                         cudaFuncAttributeMaxDynamicSharedMemorySize, SM_CONV12);
    cudaFuncSetAttribute((const void*)combine_kernel<HID, HID, false, false, false, false>,
                         cudaFuncAttributeMaxDynamicSharedMemorySize, SM_HH);
    cudaFuncSetAttribute((const void*)combine_kernel<HID, HID, false, true,  true,  true>,
                         cudaFuncAttributeMaxDynamicSharedMemorySize, SM_HH);
    cudaFuncSetAttribute((const void*)combine_kernel<HID, OUT_D, false, false, false, true>,
                         cudaFuncAttributeMaxDynamicSharedMemorySize, SM_HO);

    const int GRID_CONV = 296;   // 2 blocks/SM at 96KB smem, 148 SMs
    const int GRID_HO   = 444;   // 3 blocks/SM at 64KB smem

    const int NBU = (N_USER  + 1023) / 1024;   // 98
    const int NBM = (N_MOVIE + 1023) / 1024;   // 20

    // --- CSR build ---
    zero_counts<<<(N_USER + 255) / 256, 256>>>();
    hist_kernel<<<(NEDGE + 255) / 256, 256>>>(eu, em);
    scan_block_kernel<<<NBU, 1024>>>(p_deg_u, p_off_u, p_part_u, N_USER);
    scan_block_kernel<<<NBM, 1024>>>(p_deg_m, p_off_m, p_part_m, N_MOVIE);
    scan_partials_kernel<<<1, 128>>>(NBU, NBM);
    add_offsets_kernel<<<(N_USER + 255) / 256, 256>>>(p_off_u, p_cur_u, p_part_u, N_USER);
    add_offsets_kernel<<<(N_MOVIE + 255) / 256, 256>>>(p_off_m, p_cur_m, p_part_m, N_MOVIE);
    fill_kernel<<<(NEDGE + 255) / 256, 256>>>(eu, em);

    // --- conv1 + conv2 aggregation (gather means) ---
    gather_mean<D_IN><<<(N_USER * 32 + 255) / 256, 256>>>(
        x_movie, p_adj_u, p_off_u, p_deg_u, p_agg_user, N_USER);
    gather_mean<D_IN><<<(N_MOVIE * 32 + 255) / 256, 256>>>(
        x_user, p_adj_m, p_off_m, p_deg_m, p_agg_movie, N_MOVIE);

    // conv1: user_x = relu(agg_user @ W1l + x_user @ W1r + b1)
    combine_kernel<D_IN, HID, true, true, true, true>
        <<<GRID_CONV, 256, SM_CONV12>>>(
            p_agg_user, x_user, W1l, W1r, b1, p_user_x, N_USER);

    // conv2: movie_x = relu(agg_movie @ W2l + x_movie @ W2r + b2)
    combine_kernel<D_IN, HID, true, true, true, true>
        <<<GRID_CONV, 256, SM_CONV12>>>(
            p_agg_movie, x_movie, W2l, W2r, b2, p_movie_x, N_MOVIE);

    // Project movies BEFORE aggregation: movieP = movie_x @ W3l
    combine_kernel<HID, HID, false, false, false, false>
        <<<GRID_CONV, 256, SM_HH>>>(
            nullptr, p_movie_x, nullptr, W3l, nullptr, p_movieP, N_MOVIE);

    // conv3 aggregation (gather mean of projected features)
    gather_mean<HID><<<(N_USER * 32 + 255) / 256, 256>>>(
        p_movieP, p_adj_u, p_off_u, p_deg_u, p_agg_user2, N_USER);

    // conv3: user_h = relu(agg_user2 + user_x @ W3r + b3)
    combine_kernel<HID, HID, false, true, true, true>
        <<<GRID_CONV, 256, SM_HH>>>(
            p_agg_user2, p_user_x, nullptr, W3r, b3, p_user_h, N_USER);

    // out_user = user_h @ Wlin1 + blin1
    combine_kernel<HID, OUT_D, false, false, false, true>
        <<<GRID_HO, 256, SM_HO>>>(
            nullptr, p_user_h, nullptr, Wlin1, blin1, out_user, N_USER);

    // out_movie = movie_x @ Wlin2 + blin2
    combine_kernel<HID, OUT_D, false, false, false, true>
        <<<GRID_HO, 256, SM_HO>>>(
            nullptr, p_movie_x, nullptr, Wlin2, blin2, out_movie, N_MOVIE);
}